// round 8
// baseline (speedup 1.0000x reference)
#include <cuda_runtime.h>
#include <cstdint>

// Problem constants (fixed by the reference: B=4, N=262144, G=128)
#define NBATCH 4
#define NPART  262144           // 2^18
#define TOTALP (NBATCH * NPART) // 1048576
#define GDIM   128
#define BOUNDC 3
#define TPB    16               // tiles per axis (tile = 8 nodes)
#define NKEY   (NBATCH * TPB * TPB * TPB)   // 16384
#define HALO   11               // 8 + 1 low + 2 high
#define HALO3  (HALO * HALO * HALO)         // 1331

__constant__ float kDT = 5e-4f;

// Scratch (static __device__ — allowed)
__device__ int      g_counts[NKEY];
__device__ int      g_start[NKEY];
__device__ uint32_t g_keyrank[TOTALP];   // key<<18 | rank  (14+18 = 32 bits, UNSIGNED)
__device__ float4   g_xs4[TOTALP];       // sorted {x,y,z, pid-as-bits}

// ---------------------------------------------------------------------------
__global__ void zero_kernel()
{
    const int t = blockIdx.x * blockDim.x + threadIdx.x;
    if (t < NKEY) g_counts[t] = 0;
}

// key = (b<<12)|(cx<<8)|(cy<<4)|cz  with c* = floor(x*16) (exact: x*16 and
// x*128 are exact power-of-two scalings, so cell and stencil base agree).
__global__ void histo_kernel(const float* __restrict__ x)
{
    const int pid = blockIdx.x * blockDim.x + threadIdx.x;
    if (pid >= TOTALP) return;
    const int b = pid >> 18;
    const float x0 = x[pid * 3 + 0];
    const float x1 = x[pid * 3 + 1];
    const float x2 = x[pid * 3 + 2];
    const int cx = min(max((int)(x0 * (float)TPB), 0), TPB - 1);
    const int cy = min(max((int)(x1 * (float)TPB), 0), TPB - 1);
    const int cz = min(max((int)(x2 * (float)TPB), 0), TPB - 1);
    const uint32_t key = (uint32_t)((b << 12) | (cx << 8) | (cy << 4) | cz);
    const uint32_t r = (uint32_t)atomicAdd(&g_counts[key], 1);
    g_keyrank[pid] = (key << 18) | r;
}

// Exclusive scan of g_counts[16384] -> g_start, one block of 1024 threads.
__global__ void scan_kernel()
{
    __shared__ int ps[1024];
    const int t = threadIdx.x;
    const int base = t * 16;
    int loc[16];
    int s = 0;
    #pragma unroll
    for (int i = 0; i < 16; i++) { loc[i] = g_counts[base + i]; s += loc[i]; }
    ps[t] = s;
    __syncthreads();
    for (int d = 1; d < 1024; d <<= 1) {
        int v = 0;
        if (t >= d) v = ps[t - d];
        __syncthreads();
        if (t >= d) ps[t] += v;
        __syncthreads();
    }
    int run = (t == 0) ? 0 : ps[t - 1];
    #pragma unroll
    for (int i = 0; i < 16; i++) { g_start[base + i] = run; run += loc[i]; }
}

__global__ void scatter_kernel(const float* __restrict__ x)
{
    const int pid = blockIdx.x * blockDim.x + threadIdx.x;
    if (pid >= TOTALP) return;
    const uint32_t kr = g_keyrank[pid];
    const uint32_t key = kr >> 18;              // logical shift (unsigned)
    const uint32_t rank = kr & 0x3FFFFu;
    const int pos = g_start[key] + (int)rank;
    g_xs4[pos] = make_float4(x[pid * 3 + 0], x[pid * 3 + 1], x[pid * 3 + 2],
                             __int_as_float(pid));
}

// ---------------------------------------------------------------------------
// One block per tile key. Load the 11^3 halo once (grid_op applied per node,
// no redundancy), then gather each particle's 27 nodes from shared memory.
// ---------------------------------------------------------------------------
__global__ __launch_bounds__(128)
void tile_kernel(const float* __restrict__ friction,
                 const float* __restrict__ pred,
                 const float* __restrict__ collider_floor,
                 const int*   __restrict__ statics,
                 float* __restrict__ out)
{
    __shared__ float4 s[HALO3];   // 21296 B

    const int key = blockIdx.x;
    const int b  = key >> 12;
    const int cx = (key >> 8) & 15;
    const int cy = (key >> 4) & 15;
    const int cz = key & 15;
    const int tid = threadIdx.x;

    const float dx = 1.0f / (float)GDIM;
    const float mu  = friction[b];
    const float thr = collider_floor[b] + (float)BOUNDC * dx;

    const int t0x = 8 * cx - 1;
    const int t0y = 8 * cy - 1;
    const int t0z = 8 * cz - 1;

    const float* __restrict__ gbase =
        pred + (size_t)b * (GDIM * GDIM * GDIM * 3);

    // ---- halo load + grid_op (once per node) ----
    for (int n = tid; n < HALO3; n += 128) {
        const int li = n / (HALO * HALO);
        const int lj = (n / HALO) % HALO;
        const int lk = n % HALO;
        const int gi = min(max(t0x + li, 0), GDIM - 1);
        const int gj = min(max(t0y + lj, 0), GDIM - 1);
        const int gk = min(max(t0z + lk, 0), GDIM - 1);
        const size_t f = ((size_t)(gi * GDIM + gj) * GDIM + gk) * 3;
        float vx = gbase[f + 0];
        float vy = gbase[f + 1];
        float vz = gbase[f + 2];

        // floor Coulomb friction (normal = +y)
        if (((float)gj * dx) <= thr && vy < 0.0f) {
            const float rinv = rsqrtf(vx * vx + vz * vz + 1e-10f);
            const float sc = fmaxf(0.0f, fmaf(mu * vy, rinv, 1.0f));
            vx *= sc; vz *= sc; vy = 0.0f;
        }
        // boundary band clamps
        if ((gi < BOUNDC && vx < 0.0f) || (gi >= GDIM - BOUNDC && vx > 0.0f)) vx = 0.0f;
        if ((gj < BOUNDC && vy < 0.0f) || (gj >= GDIM - BOUNDC && vy > 0.0f)) vy = 0.0f;
        if ((gk < BOUNDC && vz < 0.0f) || (gk >= GDIM - BOUNDC && vz > 0.0f)) vz = 0.0f;

        s[n] = make_float4(vx, vy, vz, 0.0f);
    }
    __syncthreads();

    const int start = g_start[key];
    const int end   = (key == NKEY - 1) ? TOTALP : g_start[key + 1];

    for (int idx = start + tid; idx < end; idx += 128) {
        const float4 p4 = g_xs4[idx];
        const int pid = __float_as_int(p4.w);
        const float x0 = p4.x, x1 = p4.y, x2 = p4.z;

        const float u0 = x0 * (float)GDIM;
        const float u1 = x1 * (float)GDIM;
        const float u2 = x2 * (float)GDIM;
        const int bx = (int)floorf(u0 - 0.5f);
        const int by = (int)floorf(u1 - 0.5f);
        const int bz = (int)floorf(u2 - 0.5f);
        const float f0 = u0 - (float)bx;
        const float f1 = u1 - (float)by;
        const float f2 = u2 - (float)bz;

        float w0[3], w1[3], w2[3];
        w0[0] = 0.5f * (1.5f - f0) * (1.5f - f0);
        w0[1] = 0.75f - (f0 - 1.0f) * (f0 - 1.0f);
        w0[2] = 0.5f * (f0 - 0.5f) * (f0 - 0.5f);
        w1[0] = 0.5f * (1.5f - f1) * (1.5f - f1);
        w1[1] = 0.75f - (f1 - 1.0f) * (f1 - 1.0f);
        w1[2] = 0.5f * (f1 - 0.5f) * (f1 - 0.5f);
        w2[0] = 0.5f * (1.5f - f2) * (1.5f - f2);
        w2[1] = 0.75f - (f2 - 1.0f) * (f2 - 1.0f);
        w2[2] = 0.5f * (f2 - 0.5f) * (f2 - 0.5f);

        // local (halo) indices of the clamped stencil nodes
        int rx[3], ry[3], rz[3];
        #pragma unroll
        for (int c = 0; c < 3; c++) {
            rx[c] = (min(max(bx + c, 0), GDIM - 1) - t0x) * (HALO * HALO);
            ry[c] = (min(max(by + c, 0), GDIM - 1) - t0y) * HALO;
            rz[c] =  min(max(bz + c, 0), GDIM - 1) - t0z;
        }

        float accx = 0.0f, accy = 0.0f, accz = 0.0f;
        #pragma unroll
        for (int i = 0; i < 3; i++) {
            #pragma unroll
            for (int j = 0; j < 3; j++) {
                const int rij = rx[i] + ry[j];
                const float wij = w0[i] * w1[j];
                #pragma unroll
                for (int k = 0; k < 3; k++) {
                    const float4 v = s[rij + rz[k]];
                    const float w = wij * w2[k];
                    accx = fmaf(w, v.x, accx);
                    accy = fmaf(w, v.y, accy);
                    accz = fmaf(w, v.z, accz);
                }
            }
        }

        const float m = (float)statics[pid];
        accx *= m; accy *= m; accz *= m;

        float* __restrict__ out_x = out;
        float* __restrict__ out_v = out + (size_t)TOTALP * 3;
        out_x[pid * 3 + 0] = fmaf(kDT, accx, x0);
        out_x[pid * 3 + 1] = fmaf(kDT, accy, x1);
        out_x[pid * 3 + 2] = fmaf(kDT, accz, x2);
        out_v[pid * 3 + 0] = accx;
        out_v[pid * 3 + 1] = accy;
        out_v[pid * 3 + 2] = accz;
    }
}

extern "C" void kernel_launch(void* const* d_in, const int* in_sizes, int n_in,
                              void* d_out, int out_size)
{
    // metadata order: x, v, friction, pred, collider_floor, statics_enabled, step
    const float* x              = (const float*)d_in[0];
    const float* friction       = (const float*)d_in[2];
    const float* pred           = (const float*)d_in[3];
    const float* collider_floor = (const float*)d_in[4];
    const int*   statics        = (const int*)d_in[5];

    float* out = (float*)d_out;

    zero_kernel<<<(NKEY + 255) / 256, 256>>>();
    histo_kernel<<<TOTALP / 256, 256>>>(x);
    scan_kernel<<<1, 1024>>>();
    scatter_kernel<<<TOTALP / 256, 256>>>(x);
    tile_kernel<<<NKEY, 128>>>(friction, pred, collider_floor, statics, out);
}